// round 15
// baseline (speedup 1.0000x reference)
#include <cuda_runtime.h>

// CrossCompress: B=16384 rows, D=128.
// item_out   = v*(e.w_vv) + e*(v.w_ev) + bias_v
// entity_out = v*(e.w_ve) + e*(v.w_ee) + bias_e
//
// R15: persistent layout. grid=148 (1 CTA/SM on GB300-class), 256 threads.
// Warps grid-stride over 4096 four-row batches (3-4 each). Weights/biases
// loaded ONCE per warp for the whole kernel. Per-batch body identical to
// the best-measured shape (R13): 8 batched LDG.128 (MLP=8), 16-chain
// 5-level butterfly, fused combine + store. Eliminates CTA re-dispatch and
// naturally staggers load bursts across loop iterations.

#define B_ROWS   16384
#define D_DIM    128
#define RPW      4                      // rows per batch
#define NBATCH   (B_ROWS / RPW)         // 4096 batches
#define GRID     148
#define THREADS  256
#define NWARPS   (GRID * THREADS / 32)  // 1184

__global__ __launch_bounds__(THREADS)
void crosscompress_kernel(const float4* __restrict__ v_in,
                          const float4* __restrict__ e_in,
                          const float4* __restrict__ w_vv,
                          const float4* __restrict__ w_ve,
                          const float4* __restrict__ w_ev,
                          const float4* __restrict__ w_ee,
                          const float4* __restrict__ bias_v,
                          const float4* __restrict__ bias_e,
                          float4* __restrict__ out_item,
                          float4* __restrict__ out_ent)
{
    const int gtid = blockIdx.x * blockDim.x + threadIdx.x;
    const int warp = gtid >> 5;
    const int lane = gtid & 31;

    // Weights + biases once per warp for the whole kernel (L1-resident)
    const float4 wvv = __ldg(&w_vv[lane]);
    const float4 wev = __ldg(&w_ev[lane]);
    const float4 wve = __ldg(&w_ve[lane]);
    const float4 wee = __ldg(&w_ee[lane]);
    const float4 bv  = __ldg(&bias_v[lane]);
    const float4 be  = __ldg(&bias_e[lane]);

    // Grid-stride over 4-row batches
    for (int b = warp; b < NBATCH; b += NWARPS) {
        const int idx0 = (b * RPW) * 32 + lane;

        // Batched row loads: 8 independent LDG.128 (MLP=8)
        float4 v4[RPW], e4[RPW];
        #pragma unroll
        for (int r = 0; r < RPW; r++) {
            v4[r] = v_in[idx0 + r * 32];
            e4[r] = e_in[idx0 + r * 32];
        }

        // 16 independent per-lane partial dots
        float d_vv[RPW], d_ev[RPW], d_ve[RPW], d_ee[RPW];
        #pragma unroll
        for (int r = 0; r < RPW; r++) {
            d_vv[r] = e4[r].x*wvv.x + e4[r].y*wvv.y + e4[r].z*wvv.z + e4[r].w*wvv.w;
            d_ev[r] = v4[r].x*wev.x + v4[r].y*wev.y + v4[r].z*wev.z + v4[r].w*wev.w;
            d_ve[r] = e4[r].x*wve.x + e4[r].y*wve.y + e4[r].z*wve.z + e4[r].w*wve.w;
            d_ee[r] = v4[r].x*wee.x + v4[r].y*wee.y + v4[r].z*wee.z + v4[r].w*wee.w;
        }

        // Butterfly-reduce all 16 values (16 parallel chains per level)
        #pragma unroll
        for (int off = 16; off > 0; off >>= 1) {
            #pragma unroll
            for (int r = 0; r < RPW; r++) {
                d_vv[r] += __shfl_xor_sync(0xFFFFFFFFu, d_vv[r], off);
                d_ev[r] += __shfl_xor_sync(0xFFFFFFFFu, d_ev[r], off);
                d_ve[r] += __shfl_xor_sync(0xFFFFFFFFu, d_ve[r], off);
                d_ee[r] += __shfl_xor_sync(0xFFFFFFFFu, d_ee[r], off);
            }
        }

        // Combine + store
        #pragma unroll
        for (int r = 0; r < RPW; r++) {
            const int idx = idx0 + r * 32;
            float4 oi, oe;
            oi.x = v4[r].x*d_vv[r] + e4[r].x*d_ev[r] + bv.x;
            oi.y = v4[r].y*d_vv[r] + e4[r].y*d_ev[r] + bv.y;
            oi.z = v4[r].z*d_vv[r] + e4[r].z*d_ev[r] + bv.z;
            oi.w = v4[r].w*d_vv[r] + e4[r].w*d_ev[r] + bv.w;
            oe.x = v4[r].x*d_ve[r] + e4[r].x*d_ee[r] + be.x;
            oe.y = v4[r].y*d_ve[r] + e4[r].y*d_ee[r] + be.y;
            oe.z = v4[r].z*d_ve[r] + e4[r].z*d_ee[r] + be.z;
            oe.w = v4[r].w*d_ve[r] + e4[r].w*d_ee[r] + be.w;
            out_item[idx] = oi;
            out_ent[idx]  = oe;
        }
    }
}

extern "C" void kernel_launch(void* const* d_in, const int* in_sizes, int n_in,
                              void* d_out, int out_size)
{
    const float4* v_in   = (const float4*)d_in[0];
    const float4* e_in   = (const float4*)d_in[1];
    const float4* w_vv   = (const float4*)d_in[2];
    const float4* w_ve   = (const float4*)d_in[3];
    const float4* w_ev   = (const float4*)d_in[4];
    const float4* w_ee   = (const float4*)d_in[5];
    const float4* bias_v = (const float4*)d_in[6];
    const float4* bias_e = (const float4*)d_in[7];

    float* out = (float*)d_out;
    float4* out_item = (float4*)out;
    float4* out_ent  = (float4*)(out + B_ROWS * D_DIM);

    crosscompress_kernel<<<GRID, THREADS>>>(v_in, e_in, w_vv, w_ve, w_ev, w_ee,
                                            bias_v, bias_e, out_item, out_ent);
}

// round 17
// speedup vs baseline: 1.4723x; 1.4723x over previous
#include <cuda_runtime.h>
#include <cstdint>

// CrossCompress: B=16384 rows, D=128.
// item_out   = v*(e.w_vv) + e*(v.w_ev) + bias_v
// entity_out = v*(e.w_ve) + e*(v.w_ee) + bias_e
//
// R17: R13 geometry (best: 512 blocks x 128 thr, 2 iterations x 4 rows/warp,
// MLP=8 batched LDG.128, 16-chain butterfly, fused combine+store) + L2
// eviction policy via createpolicy/cache_hint (the encoding sm_103 ptxas
// accepts for 128-bit loads): input row loads are L2::evict_last so v/e
// stay L2-resident across graph replays while dirty output lines absorb
// eviction pressure.

#define B_ROWS 16384
#define D_DIM  128
#define RPW    4     // rows per iteration
#define NITER  2     // iterations per warp

__device__ __forceinline__ float4 ldg_el(const float4* __restrict__ p, uint64_t pol) {
    float4 r;
    asm volatile("ld.global.nc.L2::cache_hint.v4.f32 {%0,%1,%2,%3}, [%4], %5;"
                 : "=f"(r.x), "=f"(r.y), "=f"(r.z), "=f"(r.w)
                 : "l"(p), "l"(pol));
    return r;
}

__global__ __launch_bounds__(128)
void crosscompress_kernel(const float4* __restrict__ v_in,
                          const float4* __restrict__ e_in,
                          const float4* __restrict__ w_vv,
                          const float4* __restrict__ w_ve,
                          const float4* __restrict__ w_ev,
                          const float4* __restrict__ w_ee,
                          const float4* __restrict__ bias_v,
                          const float4* __restrict__ bias_e,
                          float4* __restrict__ out_item,
                          float4* __restrict__ out_ent)
{
    const int gtid = blockIdx.x * blockDim.x + threadIdx.x;
    const int warp = gtid >> 5;
    const int lane = gtid & 31;

    // L2 evict-last policy for input streams (built once per thread)
    uint64_t pol;
    asm("createpolicy.fractional.L2::evict_last.b64 %0, 1.0;" : "=l"(pol));

    // Weights + biases once per warp (L1-resident)
    const float4 wvv = __ldg(&w_vv[lane]);
    const float4 wev = __ldg(&w_ev[lane]);
    const float4 wve = __ldg(&w_ve[lane]);
    const float4 wee = __ldg(&w_ee[lane]);
    const float4 bv  = __ldg(&bias_v[lane]);
    const float4 be  = __ldg(&bias_e[lane]);

    #pragma unroll
    for (int it = 0; it < NITER; it++) {
        const int idx0 = ((warp * NITER + it) * RPW) * 32 + lane;

        // Batched row loads: 8 independent LDG.128, L2 evict-last policy
        float4 v4[RPW], e4[RPW];
        #pragma unroll
        for (int r = 0; r < RPW; r++) {
            v4[r] = ldg_el(&v_in[idx0 + r * 32], pol);
            e4[r] = ldg_el(&e_in[idx0 + r * 32], pol);
        }

        // 16 independent per-lane partial dots
        float d_vv[RPW], d_ev[RPW], d_ve[RPW], d_ee[RPW];
        #pragma unroll
        for (int r = 0; r < RPW; r++) {
            d_vv[r] = e4[r].x*wvv.x + e4[r].y*wvv.y + e4[r].z*wvv.z + e4[r].w*wvv.w;
            d_ev[r] = v4[r].x*wev.x + v4[r].y*wev.y + v4[r].z*wev.z + v4[r].w*wev.w;
            d_ve[r] = e4[r].x*wve.x + e4[r].y*wve.y + e4[r].z*wve.z + e4[r].w*wve.w;
            d_ee[r] = v4[r].x*wee.x + v4[r].y*wee.y + v4[r].z*wee.z + v4[r].w*wee.w;
        }

        // Butterfly-reduce all 16 values (16 parallel chains per level)
        #pragma unroll
        for (int off = 16; off > 0; off >>= 1) {
            #pragma unroll
            for (int r = 0; r < RPW; r++) {
                d_vv[r] += __shfl_xor_sync(0xFFFFFFFFu, d_vv[r], off);
                d_ev[r] += __shfl_xor_sync(0xFFFFFFFFu, d_ev[r], off);
                d_ve[r] += __shfl_xor_sync(0xFFFFFFFFu, d_ve[r], off);
                d_ee[r] += __shfl_xor_sync(0xFFFFFFFFu, d_ee[r], off);
            }
        }

        // Combine + store
        #pragma unroll
        for (int r = 0; r < RPW; r++) {
            const int idx = idx0 + r * 32;
            float4 oi, oe;
            oi.x = v4[r].x*d_vv[r] + e4[r].x*d_ev[r] + bv.x;
            oi.y = v4[r].y*d_vv[r] + e4[r].y*d_ev[r] + bv.y;
            oi.z = v4[r].z*d_vv[r] + e4[r].z*d_ev[r] + bv.z;
            oi.w = v4[r].w*d_vv[r] + e4[r].w*d_ev[r] + bv.w;
            oe.x = v4[r].x*d_ve[r] + e4[r].x*d_ee[r] + be.x;
            oe.y = v4[r].y*d_ve[r] + e4[r].y*d_ee[r] + be.y;
            oe.z = v4[r].z*d_ve[r] + e4[r].z*d_ee[r] + be.z;
            oe.w = v4[r].w*d_ve[r] + e4[r].w*d_ee[r] + be.w;
            out_item[idx] = oi;
            out_ent[idx]  = oe;
        }
    }
}

extern "C" void kernel_launch(void* const* d_in, const int* in_sizes, int n_in,
                              void* d_out, int out_size)
{
    const float4* v_in   = (const float4*)d_in[0];
    const float4* e_in   = (const float4*)d_in[1];
    const float4* w_vv   = (const float4*)d_in[2];
    const float4* w_ve   = (const float4*)d_in[3];
    const float4* w_ev   = (const float4*)d_in[4];
    const float4* w_ee   = (const float4*)d_in[5];
    const float4* bias_v = (const float4*)d_in[6];
    const float4* bias_e = (const float4*)d_in[7];

    float* out = (float*)d_out;
    float4* out_item = (float4*)out;
    float4* out_ent  = (float4*)(out + B_ROWS * D_DIM);

    // 4 warps/block, 8 rows/warp (2 iter x 4) -> 32 rows/block -> 512 blocks
    const int threads = 128;
    const int blocks  = B_ROWS / (4 * RPW * NITER);   // 512

    crosscompress_kernel<<<blocks, threads>>>(v_in, e_in, w_vv, w_ve, w_ev, w_ee,
                                              bias_v, bias_e, out_item, out_ent);
}